// round 16
// baseline (speedup 1.0000x reference)
#include <cuda_runtime.h>
#include <math.h>

#define BATCH 512
#define DIM   256
#define NPIX  196
#define HEADS 4
#define KD    16
#define VD    64
#define QKVO  96
#define CH    64
#define N4    49

typedef unsigned long long ull;

// packed fp32x2 FMA (SASS FFMA2) — only reachable via PTX
#define FMA2(d, a, b) asm("fma.rn.f32x2 %0, %1, %2, %0;" : "+l"(d) : "l"(a), "l"(b))
#define PACK2(u, f)   asm("mov.b64 %0, {%1, %1};" : "=l"(u) : "f"(f))
#define UNPACK2(lo, hi, u) asm("mov.b64 {%0, %1}, %2;" : "=f"(lo), "=f"(hi) : "l"(u))
#define EX2(d, s)     asm("ex2.approx.f32 %0, %1;" : "=f"(d) : "f"(s))

#define LOG2E 1.4426950408889634f

union F4 {
    float4 v;
    ull u[2];
    float f[4];
};

// ---------------- device scratch ----------------
__device__ float g_bias[HEADS * NPIX * NPIX];       // pre-multiplied by log2(e)
__device__ float g_pwT[DIM * DIM];                  // proj weights [c][o], BN-scale folded
__device__ float g_pt[DIM];                         // proj BN shift
__device__ float g_y[(size_t)BATCH * DIM * NPIX];   // relu'd head outputs

// ---------------- dummy kernels (keep ncu capture slot on k_attn) ----------------
__global__ void k_nop1() {}
__global__ void k_nop2() {}

// ---------------- kernel 0: prep ----------------
__global__ void __launch_bounds__(256) k_pre(
    const float* __restrict__ ab, const int* __restrict__ bidx,
    const float* __restrict__ pw, const float* __restrict__ pg,
    const float* __restrict__ pb, const float* __restrict__ prm,
    const float* __restrict__ prv)
{
    int i = blockIdx.x * 256 + threadIdx.x;
    if (i < HEADS * NPIX * NPIX) {
        int h = i / (NPIX * NPIX);
        int nm = i % (NPIX * NPIX);
        g_bias[i] = ab[h * NPIX + bidx[nm]] * LOG2E;
    }
    if (i < DIM) {
        float s = pg[i] * rsqrtf(prv[i] + 1e-5f);
        g_pt[i] = pb[i] - prm[i] * s;
    }
    if (i < DIM * DIM) {
        int o = i >> 8, c = i & 255;
        float s = pg[o] * rsqrtf(prv[o] + 1e-5f);
        g_pwT[c * DIM + o] = pw[i] * s;
    }
}

// ---------------- kernel 1: cascaded attention, 1024 threads / CTA ----------------
#define OFF_P    0
#define OFF_WT   0        // 64 x 100 = 6400
#define OFF_FEAT 6400     // 64 x 196 = 12544 (ends 18944)
#define OFF_K    19216    // 16 x 196
#define OFF_Q    22352    // 16 x 196 x 2 (duplicated pairs)
#define OFF_V    28624    // 64 x 196
#define OFF_OUT  41168    // 64 x 196 (rows 0..15 double as qtmp)
#define OFF_QS   53712
#define OFF_QT   53808
#define OFF_DWS  53904
#define OFF_DWT  53920
#define OFF_DWW  53936    // 16 x 25
#define SMEM_FLOATS 54436
#define SMEM_BYTES  (SMEM_FLOATS * 4)
#define NT 1024

__global__ void __launch_bounds__(NT, 1) k_attn(
    const float* __restrict__ x,
    const float* __restrict__ qkv_w, const float* __restrict__ qkv_g,
    const float* __restrict__ qkv_b, const float* __restrict__ qkv_rm,
    const float* __restrict__ qkv_rv,
    const float* __restrict__ dw_w, const float* __restrict__ dw_g,
    const float* __restrict__ dw_b, const float* __restrict__ dw_rm,
    const float* __restrict__ dw_rv)
{
    extern __shared__ float sm[];
    float* Psm  = sm + OFF_P;
    float* wT   = sm + OFF_WT;
    float* feat = sm + OFF_FEAT;
    float* kbuf = sm + OFF_K;
    float2* qbuf2 = reinterpret_cast<float2*>(sm + OFF_Q);
    const ull* qbufu = reinterpret_cast<const ull*>(sm + OFF_Q);
    float* vbuf = sm + OFF_V;
    float* obuf = sm + OFF_OUT;
    float* qs   = sm + OFF_QS;
    float* qt   = sm + OFF_QT;
    float* dws  = sm + OFF_DWS;
    float* dwt  = sm + OFF_DWT;
    float* dww  = sm + OFF_DWW;

    const int b = blockIdx.x;
    const int t = threadIdx.x;

    for (int h = 0; h < HEADS; ++h) {
        // ---- phase 0: feat = (h==0 ? chunk0 : prev_out + chunk_h) ----
        {
            const float4* xc = reinterpret_cast<const float4*>(x) + ((size_t)b * DIM + h * CH) * N4;
            float4* f4 = reinterpret_cast<float4*>(feat);
            const float4* o4 = reinterpret_cast<const float4*>(obuf);
            if (h == 0) {
                for (int i = t; i < CH * N4; i += NT) f4[i] = xc[i];
            } else {
                for (int i = t; i < CH * N4; i += NT) {
                    float4 a = xc[i]; float4 c = o4[i];
                    a.x += c.x; a.y += c.y; a.z += c.z; a.w += c.w;
                    f4[i] = a;
                }
            }
        }
        // ---- phase 1: weights + BN folding ----
        for (int i = t; i < QKVO * CH; i += NT) {
            int c = i & 63, o = i >> 6;
            wT[c * 100 + o] = qkv_w[h * QKVO * CH + o * CH + c];
        }
        if (t < QKVO) {
            float s = qkv_g[h * QKVO + t] * rsqrtf(qkv_rv[h * QKVO + t] + 1e-5f);
            qs[t] = s;
            qt[t] = qkv_b[h * QKVO + t] - qkv_rm[h * QKVO + t] * s;
        } else if (t < QKVO + KD) {
            int d = t - QKVO;
            float s = dw_g[h * KD + d] * rsqrtf(dw_rv[h * KD + d] + 1e-5f);
            dws[d] = s;
            dwt[d] = dw_b[h * KD + d] - dw_rm[h * KD + d] * s;
        }
        for (int i = t; i < KD * 25; i += NT) dww[i] = dw_w[h * KD * 25 + i];
        __syncthreads();

        // ---- phase 2: QKV GEMM, thread tile 8o x 4n (12 ot x 49 nt = 588 active) ----
        if (t < 12 * N4) {
            const int ot = t / N4, nt = t % N4;
            const float4* f4 = reinterpret_cast<const float4*>(feat);
            const ull* wu = reinterpret_cast<const ull*>(wT);   // pitch 50 ull
            ull acc[4][4];
            #pragma unroll
            for (int g = 0; g < 4; ++g)
                #pragma unroll
                for (int j = 0; j < 4; ++j) acc[g][j] = 0ull;
            #pragma unroll 4
            for (int c = 0; c < CH; ++c) {
                F4 fv; fv.v = f4[c * N4 + nt];
                ull fp[4];
                #pragma unroll
                for (int j = 0; j < 4; ++j) PACK2(fp[j], fv.f[j]);
                #pragma unroll
                for (int g = 0; g < 4; ++g) {
                    ull wv = wu[c * 50 + ot * 4 + g];
                    #pragma unroll
                    for (int j = 0; j < 4; ++j)
                        FMA2(acc[g][j], wv, fp[j]);
                }
            }
            #pragma unroll
            for (int g = 0; g < 4; ++g) {
                float lo[4], hi[4];
                #pragma unroll
                for (int j = 0; j < 4; ++j) UNPACK2(lo[j], hi[j], acc[g][j]);
                #pragma unroll
                for (int half = 0; half < 2; ++half) {
                    const int o = ot * 8 + g * 2 + half;
                    const float* src = half ? hi : lo;
                    float s = qs[o], tt = qt[o];
                    float4 r = make_float4(fmaf(src[0], s, tt), fmaf(src[1], s, tt),
                                           fmaf(src[2], s, tt), fmaf(src[3], s, tt));
                    float4* dst;
                    if (o < KD)          dst = reinterpret_cast<float4*>(obuf) + o * N4;
                    else if (o < 2 * KD) dst = reinterpret_cast<float4*>(kbuf) + (o - KD) * N4;
                    else                 dst = reinterpret_cast<float4*>(vbuf) + (o - 2 * KD) * N4;
                    dst[nt] = r;
                }
            }
        }
        __syncthreads();

        // ---- phase 3: depthwise 5x5 conv on qtmp(obuf rows0-15) -> qbuf (paired) ----
        for (int i = t; i < KD * NPIX; i += NT) {
            int d = i / NPIX, n = i % NPIX;
            int yy0 = n / 14, xx0 = n % 14;
            const float* qr = obuf + d * NPIX;
            const float* wr = dww + d * 25;
            float s = 0.f;
            #pragma unroll
            for (int dy = -2; dy <= 2; ++dy) {
                int yy = yy0 + dy;
                if ((unsigned)yy < 14u) {
                    #pragma unroll
                    for (int dx = -2; dx <= 2; ++dx) {
                        int xx = xx0 + dx;
                        if ((unsigned)xx < 14u)
                            s = fmaf(wr[(dy + 2) * 5 + (dx + 2)], qr[yy * 14 + xx], s);
                    }
                }
            }
            float v = fmaf(s, dws[d], dwt[d]) * (0.25f * LOG2E);
            qbuf2[i] = make_float2(v, v);
        }
        __syncthreads();

        // ---- phase 4: attention in 2 row-blocks of 98; softmax fused ----
        for (int np = 0; np < 2; ++np) {
            const int n0 = np * 98;
            // 4a: P = exp2(q.k + bias), thread tile 7r x 4m (686 active)
            if (t < 14 * N4) {
                const int rt = t / N4, mt = t % N4;
                const int r0 = rt * 7;
                const float4* k4 = reinterpret_cast<const float4*>(kbuf);
                const float4* b4 = reinterpret_cast<const float4*>(g_bias) + ((size_t)h * NPIX + n0) * N4;
                float4* P4 = reinterpret_cast<float4*>(Psm);
                ull acc[7][2];
                #pragma unroll
                for (int i = 0; i < 7; ++i) {
                    F4 bv; bv.v = b4[(r0 + i) * N4 + mt];
                    acc[i][0] = bv.u[0]; acc[i][1] = bv.u[1];
                }
                #pragma unroll 4
                for (int d = 0; d < KD; ++d) {
                    F4 kv; kv.v = k4[d * N4 + mt];
                    const ull* qp = qbufu + d * NPIX + n0 + r0;
                    #pragma unroll
                    for (int i = 0; i < 7; ++i) {
                        ull qq = qp[i];
                        FMA2(acc[i][0], qq, kv.u[0]);
                        FMA2(acc[i][1], qq, kv.u[1]);
                    }
                }
                #pragma unroll
                for (int i = 0; i < 7; ++i) {
                    F4 r; r.u[0] = acc[i][0]; r.u[1] = acc[i][1];
                    F4 e;
                    EX2(e.f[0], r.f[0]);
                    EX2(e.f[1], r.f[1]);
                    EX2(e.f[2], r.f[2]);
                    EX2(e.f[3], r.f[3]);
                    P4[(r0 + i) * N4 + mt] = e.v;
                }
            }
            __syncthreads();
            // 4c: out = V @ P^T with fused row-sum; pair-split over m.
            // t = 2u+g : u -> (dg, rt), g selects m4 parity. 784 active.
            // Partners reduce via shfl_xor(1); g=0 stores row rt, g=1 row rt+49.
            if (t < 2 * 8 * N4) {
                const int g = t & 1, u = t >> 1;
                const int dg = u / N4, rt = u % N4;
                const int d0 = dg * 8;
                const float4* v4 = reinterpret_cast<const float4*>(vbuf) + d0 * N4;
                const float4* P1 = reinterpret_cast<const float4*>(Psm) + rt * N4;
                const float4* P2 = reinterpret_cast<const float4*>(Psm) + (rt + 49) * N4;
                ull one; PACK2(one, 1.0f);
                ull acc1[8], acc2[8], sum1 = 0ull, sum2 = 0ull;
                #pragma unroll
                for (int j = 0; j < 8; ++j) { acc1[j] = 0ull; acc2[j] = 0ull; }
                #pragma unroll 5
                for (int m4 = g; m4 < N4; m4 += 2) {
                    F4 p1; p1.v = P1[m4];
                    F4 p2; p2.v = P2[m4];
                    FMA2(sum1, p1.u[0], one);
                    FMA2(sum1, p1.u[1], one);
                    FMA2(sum2, p2.u[0], one);
                    FMA2(sum2, p2.u[1], one);
                    #pragma unroll
                    for (int j = 0; j < 8; ++j) {
                        F4 vv; vv.v = v4[j * N4 + m4];
                        FMA2(acc1[j], p1.u[0], vv.u[0]);
                        FMA2(acc1[j], p1.u[1], vv.u[1]);
                        FMA2(acc2[j], p2.u[0], vv.u[0]);
                        FMA2(acc2[j], p2.u[1], vv.u[1]);
                    }
                }
                const unsigned mask = __activemask();
                float r1[8], r2[8];
                #pragma unroll
                for (int j = 0; j < 8; ++j) {
                    float a0, a1;
                    UNPACK2(a0, a1, acc1[j]);
                    float v1 = a0 + a1;
                    r1[j] = v1 + __shfl_xor_sync(mask, v1, 1);
                    UNPACK2(a0, a1, acc2[j]);
                    float v2 = a0 + a1;
                    r2[j] = v2 + __shfl_xor_sync(mask, v2, 1);
                }
                float s0, s1;
                UNPACK2(s0, s1, sum1);
                float ts1 = s0 + s1;
                ts1 += __shfl_xor_sync(mask, ts1, 1);
                UNPACK2(s0, s1, sum2);
                float ts2 = s0 + s1;
                ts2 += __shfl_xor_sync(mask, ts2, 1);

                const float* rr = g ? r2 : r1;
                const float il = 1.f / (g ? ts2 : ts1);
                const int nn = n0 + rt + (g ? 49 : 0);
                float* gy = g_y + ((size_t)b * DIM + h * CH + d0) * NPIX + nn;
                #pragma unroll
                for (int j = 0; j < 8; ++j) {
                    float val = rr[j] * il;
                    obuf[(d0 + j) * NPIX + nn] = val;
                    gy[j * NPIX] = fmaxf(val, 0.f);
                }
            }
            __syncthreads();
        }
    }
}

// ---------------- kernel 2: proj GEMM + BN (R12 version) ----------------
// grid (512, 4): CTA = one batch x 64-o block, 512 threads, 2 CTAs/SM (<=64 regs)
// thread tile (8o x 4n): 8 ot x 49 nt = 392 active
#define PROJ_SMEM ((12544 + 4096) * 4)
__global__ void __launch_bounds__(512, 2) k_proj(float* __restrict__ out)
{
    extern __shared__ float sm[];
    float* y_s = sm;            // 64 x 196
    float* w_s = sm + 12544;    // 64c x 64o

    const int b = blockIdx.x;
    const int ob = blockIdx.y;
    const int t = threadIdx.x;

    const bool act = (t < 8 * N4);
    const int ot = t / N4, nt = t % N4;

    ull acc[4][4];   // 4 o-pairs x 4 n
    #pragma unroll
    for (int p = 0; p < 4; ++p)
        #pragma unroll
        for (int j = 0; j < 4; ++j) acc[p][j] = 0ull;

    for (int cb = 0; cb < 4; ++cb) {
        __syncthreads();
        {
            const float4* ysrc = reinterpret_cast<const float4*>(g_y) + ((size_t)b * DIM + cb * 64) * N4;
            float4* yd = reinterpret_cast<float4*>(y_s);
            for (int i = t; i < 64 * N4; i += 512) yd[i] = ysrc[i];
            const float4* wsrc = reinterpret_cast<const float4*>(g_pwT);
            float4* wd = reinterpret_cast<float4*>(w_s);
            for (int i = t; i < 1024; i += 512) {
                int c = i >> 4, o4 = i & 15;
                wd[i] = wsrc[((cb * 64 + c) * DIM + ob * 64) / 4 + o4];
            }
        }
        __syncthreads();

        if (act) {
            const float4* y4 = reinterpret_cast<const float4*>(y_s);
            const float4* w4 = reinterpret_cast<const float4*>(w_s);
            #pragma unroll 2
            for (int c = 0; c < 64; ++c) {
                F4 yv; yv.v = y4[c * N4 + nt];
                ull yp[4];
                #pragma unroll
                for (int j = 0; j < 4; ++j) PACK2(yp[j], yv.f[j]);
                #pragma unroll
                for (int g = 0; g < 2; ++g) {
                    F4 wv; wv.v = w4[c * 16 + ot * 2 + g];
                    #pragma unroll
                    for (int half = 0; half < 2; ++half) {
                        const int p = g * 2 + half;
                        #pragma unroll
                        for (int j = 0; j < 4; ++j)
                            FMA2(acc[p][j], wv.u[half], yp[j]);
                    }
                }
            }
        }
    }

    if (act) {
        float4* out4 = reinterpret_cast<float4*>(out);
        #pragma unroll
        for (int p = 0; p < 4; ++p) {
            float lo[4], hi[4];
            #pragma unroll
            for (int j = 0; j < 4; ++j) UNPACK2(lo[j], hi[j], acc[p][j]);
            #pragma unroll
            for (int half = 0; half < 2; ++half) {
                int og = ob * 64 + ot * 8 + p * 2 + half;
                float tt = g_pt[og];
                const float* src = half ? hi : lo;
                out4[((size_t)b * DIM + og) * N4 + nt] =
                    make_float4(src[0] + tt, src[1] + tt, src[2] + tt, src[3] + tt);
            }
        }
    }
}

// ---------------- launcher ----------------
extern "C" void kernel_launch(void* const* d_in, const int* in_sizes, int n_in,
                              void* d_out, int out_size)
{
    const float* x       = (const float*)d_in[0];
    const float* qkv_w   = (const float*)d_in[1];
    const float* qkv_g   = (const float*)d_in[2];
    const float* qkv_b   = (const float*)d_in[3];
    const float* qkv_rm  = (const float*)d_in[4];
    const float* qkv_rv  = (const float*)d_in[5];
    const float* dw_w    = (const float*)d_in[6];
    const float* dw_g    = (const float*)d_in[7];
    const float* dw_b    = (const float*)d_in[8];
    const float* dw_rm   = (const float*)d_in[9];
    const float* dw_rv   = (const float*)d_in[10];
    const float* proj_w  = (const float*)d_in[11];
    const float* proj_g  = (const float*)d_in[12];
    const float* proj_b  = (const float*)d_in[13];
    const float* proj_rm = (const float*)d_in[14];
    const float* proj_rv = (const float*)d_in[15];
    const float* ab      = (const float*)d_in[16];
    const int*   bidx    = (const int*)d_in[17];
    float* out = (float*)d_out;

    cudaFuncSetAttribute(k_attn, cudaFuncAttributeMaxDynamicSharedMemorySize, SMEM_BYTES);
    cudaFuncSetAttribute(k_proj, cudaFuncAttributeMaxDynamicSharedMemorySize, PROJ_SMEM);

    k_nop1<<<1, 32>>>();
    k_nop2<<<1, 32>>>();
    k_pre<<<(HEADS * NPIX * NPIX + 255) / 256, 256>>>(ab, bidx, proj_w, proj_g, proj_b, proj_rm, proj_rv);
    k_attn<<<BATCH, NT, SMEM_BYTES>>>(x, qkv_w, qkv_g, qkv_b, qkv_rm, qkv_rv,
                                      dw_w, dw_g, dw_b, dw_rm, dw_rv);
    k_proj<<<dim3(BATCH, 4), 512, PROJ_SMEM>>>(out);
}

// round 17
// speedup vs baseline: 1.0630x; 1.0630x over previous
#include <cuda_runtime.h>
#include <math.h>

#define BATCH 512
#define DIM   256
#define NPIX  196
#define HEADS 4
#define KD    16
#define VD    64
#define QKVO  96
#define CH    64
#define N4    49

typedef unsigned long long ull;

// packed fp32x2 FMA (SASS FFMA2) — only reachable via PTX
#define FMA2(d, a, b) asm("fma.rn.f32x2 %0, %1, %2, %0;" : "+l"(d) : "l"(a), "l"(b))
#define PACK2(u, f)   asm("mov.b64 %0, {%1, %1};" : "=l"(u) : "f"(f))
#define UNPACK2(lo, hi, u) asm("mov.b64 {%0, %1}, %2;" : "=f"(lo), "=f"(hi) : "l"(u))
#define EX2(d, s)     asm("ex2.approx.f32 %0, %1;" : "=f"(d) : "f"(s))

#define LOG2E 1.4426950408889634f

union F4 {
    float4 v;
    ull u[2];
    float f[4];
};

// ---------------- device scratch ----------------
__device__ float g_bias[HEADS * NPIX * NPIX];       // pre-multiplied by log2(e)
__device__ float g_pwT[DIM * DIM];                  // proj weights [c][o], BN-scale folded
__device__ float g_pt[DIM];                         // proj BN shift
__device__ float g_y[(size_t)BATCH * DIM * NPIX];   // relu'd head outputs

// ---------------- kernel 0: prep ----------------
__global__ void __launch_bounds__(256) k_pre(
    const float* __restrict__ ab, const int* __restrict__ bidx,
    const float* __restrict__ pw, const float* __restrict__ pg,
    const float* __restrict__ pb, const float* __restrict__ prm,
    const float* __restrict__ prv)
{
    int i = blockIdx.x * 256 + threadIdx.x;
    if (i < HEADS * NPIX * NPIX) {
        int h = i / (NPIX * NPIX);
        int nm = i % (NPIX * NPIX);
        g_bias[i] = ab[h * NPIX + bidx[nm]] * LOG2E;
    }
    if (i < DIM) {
        float s = pg[i] * rsqrtf(prv[i] + 1e-5f);
        g_pt[i] = pb[i] - prm[i] * s;
    }
    if (i < DIM * DIM) {
        int o = i >> 8, c = i & 255;
        float s = pg[o] * rsqrtf(prv[o] + 1e-5f);
        g_pwT[c * DIM + o] = pw[i] * s;
    }
}

// ---------------- kernel 1: cascaded attention, 1024 threads / CTA ----------------
#define OFF_P    0
#define OFF_WT   0        // 64 x 100 = 6400
#define OFF_FEAT 6400     // 64 x 196 = 12544 (ends 18944)
#define OFF_K    19216    // 16 x 196
#define OFF_Q    22352    // 16 x 196 x 2 (duplicated pairs)
#define OFF_V    28624    // 64 x 196
#define OFF_OUT  41168    // 64 x 196 (rows 0..15 double as qtmp)
#define OFF_QS   53712
#define OFF_QT   53808
#define OFF_DWS  53904
#define OFF_DWT  53920
#define OFF_DWW  53936    // 16 x 25
#define SMEM_FLOATS 54436
#define SMEM_BYTES  (SMEM_FLOATS * 4)
#define NT 1024

__global__ void __launch_bounds__(NT, 1) k_attn(
    const float* __restrict__ x,
    const float* __restrict__ qkv_w, const float* __restrict__ qkv_g,
    const float* __restrict__ qkv_b, const float* __restrict__ qkv_rm,
    const float* __restrict__ qkv_rv,
    const float* __restrict__ dw_w, const float* __restrict__ dw_g,
    const float* __restrict__ dw_b, const float* __restrict__ dw_rm,
    const float* __restrict__ dw_rv)
{
    extern __shared__ float sm[];
    float* Psm  = sm + OFF_P;
    float* wT   = sm + OFF_WT;
    float* feat = sm + OFF_FEAT;
    float* kbuf = sm + OFF_K;
    float2* qbuf2 = reinterpret_cast<float2*>(sm + OFF_Q);
    const ull* qbufu = reinterpret_cast<const ull*>(sm + OFF_Q);
    float* vbuf = sm + OFF_V;
    float* obuf = sm + OFF_OUT;
    float* qs   = sm + OFF_QS;
    float* qt   = sm + OFF_QT;
    float* dws  = sm + OFF_DWS;
    float* dwt  = sm + OFF_DWT;
    float* dww  = sm + OFF_DWW;

    const int b = blockIdx.x;
    const int t = threadIdx.x;

    for (int h = 0; h < HEADS; ++h) {
        // ---- phase 0: feat = (h==0 ? chunk0 : prev_out + chunk_h) ----
        {
            const float4* xc = reinterpret_cast<const float4*>(x) + ((size_t)b * DIM + h * CH) * N4;
            float4* f4 = reinterpret_cast<float4*>(feat);
            const float4* o4 = reinterpret_cast<const float4*>(obuf);
            if (h == 0) {
                for (int i = t; i < CH * N4; i += NT) f4[i] = xc[i];
            } else {
                for (int i = t; i < CH * N4; i += NT) {
                    float4 a = xc[i]; float4 c = o4[i];
                    a.x += c.x; a.y += c.y; a.z += c.z; a.w += c.w;
                    f4[i] = a;
                }
            }
        }
        // ---- phase 1: weights + BN folding ----
        for (int i = t; i < QKVO * CH; i += NT) {
            int c = i & 63, o = i >> 6;
            wT[c * 100 + o] = qkv_w[h * QKVO * CH + o * CH + c];
        }
        if (t < QKVO) {
            float s = qkv_g[h * QKVO + t] * rsqrtf(qkv_rv[h * QKVO + t] + 1e-5f);
            qs[t] = s;
            qt[t] = qkv_b[h * QKVO + t] - qkv_rm[h * QKVO + t] * s;
        } else if (t < QKVO + KD) {
            int d = t - QKVO;
            float s = dw_g[h * KD + d] * rsqrtf(dw_rv[h * KD + d] + 1e-5f);
            dws[d] = s;
            dwt[d] = dw_b[h * KD + d] - dw_rm[h * KD + d] * s;
        }
        for (int i = t; i < KD * 25; i += NT) dww[i] = dw_w[h * KD * 25 + i];
        __syncthreads();

        // ---- phase 2: QKV GEMM, thread tile 8o x 4n (12 ot x 49 nt = 588 active) ----
        if (t < 12 * N4) {
            const int ot = t / N4, nt = t % N4;
            const float4* f4 = reinterpret_cast<const float4*>(feat);
            const ull* wu = reinterpret_cast<const ull*>(wT);   // pitch 50 ull
            ull acc[4][4];
            #pragma unroll
            for (int g = 0; g < 4; ++g)
                #pragma unroll
                for (int j = 0; j < 4; ++j) acc[g][j] = 0ull;
            #pragma unroll 4
            for (int c = 0; c < CH; ++c) {
                F4 fv; fv.v = f4[c * N4 + nt];
                ull fp[4];
                #pragma unroll
                for (int j = 0; j < 4; ++j) PACK2(fp[j], fv.f[j]);
                #pragma unroll
                for (int g = 0; g < 4; ++g) {
                    ull wv = wu[c * 50 + ot * 4 + g];
                    #pragma unroll
                    for (int j = 0; j < 4; ++j)
                        FMA2(acc[g][j], wv, fp[j]);
                }
            }
            #pragma unroll
            for (int g = 0; g < 4; ++g) {
                float lo[4], hi[4];
                #pragma unroll
                for (int j = 0; j < 4; ++j) UNPACK2(lo[j], hi[j], acc[g][j]);
                #pragma unroll
                for (int half = 0; half < 2; ++half) {
                    const int o = ot * 8 + g * 2 + half;
                    const float* src = half ? hi : lo;
                    float s = qs[o], tt = qt[o];
                    float4 r = make_float4(fmaf(src[0], s, tt), fmaf(src[1], s, tt),
                                           fmaf(src[2], s, tt), fmaf(src[3], s, tt));
                    float4* dst;
                    if (o < KD)          dst = reinterpret_cast<float4*>(obuf) + o * N4;
                    else if (o < 2 * KD) dst = reinterpret_cast<float4*>(kbuf) + (o - KD) * N4;
                    else                 dst = reinterpret_cast<float4*>(vbuf) + (o - 2 * KD) * N4;
                    dst[nt] = r;
                }
            }
        }
        __syncthreads();

        // ---- phase 3: depthwise 5x5 conv on qtmp(obuf rows0-15) -> qbuf (paired) ----
        for (int i = t; i < KD * NPIX; i += NT) {
            int d = i / NPIX, n = i % NPIX;
            int yy0 = n / 14, xx0 = n % 14;
            const float* qr = obuf + d * NPIX;
            const float* wr = dww + d * 25;
            float s = 0.f;
            #pragma unroll
            for (int dy = -2; dy <= 2; ++dy) {
                int yy = yy0 + dy;
                if ((unsigned)yy < 14u) {
                    #pragma unroll
                    for (int dx = -2; dx <= 2; ++dx) {
                        int xx = xx0 + dx;
                        if ((unsigned)xx < 14u)
                            s = fmaf(wr[(dy + 2) * 5 + (dx + 2)], qr[yy * 14 + xx], s);
                    }
                }
            }
            float v = fmaf(s, dws[d], dwt[d]) * (0.25f * LOG2E);
            qbuf2[i] = make_float2(v, v);
        }
        __syncthreads();

        // ---- phase 4: attention in 2 row-blocks of 98; softmax fused ----
        for (int np = 0; np < 2; ++np) {
            const int n0 = np * 98;
            // 4a: P = exp2(q.k + bias), thread tile 7r x 4m (686 active)
            if (t < 14 * N4) {
                const int rt = t / N4, mt = t % N4;
                const int r0 = rt * 7;
                const float4* k4 = reinterpret_cast<const float4*>(kbuf);
                const float4* b4 = reinterpret_cast<const float4*>(g_bias) + ((size_t)h * NPIX + n0) * N4;
                float4* P4 = reinterpret_cast<float4*>(Psm);
                ull acc[7][2];
                #pragma unroll
                for (int i = 0; i < 7; ++i) {
                    F4 bv; bv.v = b4[(r0 + i) * N4 + mt];
                    acc[i][0] = bv.u[0]; acc[i][1] = bv.u[1];
                }
                #pragma unroll 8
                for (int d = 0; d < KD; ++d) {
                    F4 kv; kv.v = k4[d * N4 + mt];
                    const ull* qp = qbufu + d * NPIX + n0 + r0;
                    #pragma unroll
                    for (int i = 0; i < 7; ++i) {
                        ull qq = qp[i];
                        FMA2(acc[i][0], qq, kv.u[0]);
                        FMA2(acc[i][1], qq, kv.u[1]);
                    }
                }
                #pragma unroll
                for (int i = 0; i < 7; ++i) {
                    F4 r; r.u[0] = acc[i][0]; r.u[1] = acc[i][1];
                    F4 e;
                    EX2(e.f[0], r.f[0]);
                    EX2(e.f[1], r.f[1]);
                    EX2(e.f[2], r.f[2]);
                    EX2(e.f[3], r.f[3]);
                    P4[(r0 + i) * N4 + mt] = e.v;
                }
            }
            __syncthreads();
            // 4c: out = V @ P^T with fused row-sum; tile 8d x 2 rows (392 active)
            if (t < 8 * N4) {
                const int dg = t / N4, rt = t % N4;
                const int d0 = dg * 8;
                const float4* v4 = reinterpret_cast<const float4*>(vbuf) + d0 * N4;
                const float4* P1 = reinterpret_cast<const float4*>(Psm) + rt * N4;
                const float4* P2 = reinterpret_cast<const float4*>(Psm) + (rt + 49) * N4;
                ull one; PACK2(one, 1.0f);
                ull acc1[8], acc2[8], sum1 = 0ull, sum2 = 0ull;
                #pragma unroll
                for (int j = 0; j < 8; ++j) { acc1[j] = 0ull; acc2[j] = 0ull; }
                #pragma unroll 7
                for (int m4 = 0; m4 < N4; ++m4) {
                    F4 p1; p1.v = P1[m4];
                    F4 p2; p2.v = P2[m4];
                    FMA2(sum1, p1.u[0], one);
                    FMA2(sum1, p1.u[1], one);
                    FMA2(sum2, p2.u[0], one);
                    FMA2(sum2, p2.u[1], one);
                    #pragma unroll
                    for (int j = 0; j < 8; ++j) {
                        F4 vv; vv.v = v4[j * N4 + m4];
                        FMA2(acc1[j], p1.u[0], vv.u[0]);
                        FMA2(acc1[j], p1.u[1], vv.u[1]);
                        FMA2(acc2[j], p2.u[0], vv.u[0]);
                        FMA2(acc2[j], p2.u[1], vv.u[1]);
                    }
                }
                float s0, s1;
                UNPACK2(s0, s1, sum1);
                float il1 = 1.f / (s0 + s1);
                UNPACK2(s0, s1, sum2);
                float il2 = 1.f / (s0 + s1);
                int nn1 = n0 + rt, nn2 = n0 + rt + 49;
                float* gy = g_y + ((size_t)b * DIM + h * CH + d0) * NPIX;
                #pragma unroll
                for (int j = 0; j < 8; ++j) {
                    float a0, a1;
                    UNPACK2(a0, a1, acc1[j]);
                    float val1 = (a0 + a1) * il1;
                    UNPACK2(a0, a1, acc2[j]);
                    float val2 = (a0 + a1) * il2;
                    obuf[(d0 + j) * NPIX + nn1] = val1;
                    obuf[(d0 + j) * NPIX + nn2] = val2;
                    gy[j * NPIX + nn1] = fmaxf(val1, 0.f);
                    gy[j * NPIX + nn2] = fmaxf(val2, 0.f);
                }
            }
            __syncthreads();
        }
    }
}

// ---------------- kernel 2: proj GEMM + BN (R12 version) ----------------
// grid (512, 4): CTA = one batch x 64-o block, 512 threads, 2 CTAs/SM (<=64 regs)
// thread tile (8o x 4n): 8 ot x 49 nt = 392 active
#define PROJ_SMEM ((12544 + 4096) * 4)
__global__ void __launch_bounds__(512, 2) k_proj(float* __restrict__ out)
{
    extern __shared__ float sm[];
    float* y_s = sm;            // 64 x 196
    float* w_s = sm + 12544;    // 64c x 64o

    const int b = blockIdx.x;
    const int ob = blockIdx.y;
    const int t = threadIdx.x;

    const bool act = (t < 8 * N4);
    const int ot = t / N4, nt = t % N4;

    ull acc[4][4];   // 4 o-pairs x 4 n
    #pragma unroll
    for (int p = 0; p < 4; ++p)
        #pragma unroll
        for (int j = 0; j < 4; ++j) acc[p][j] = 0ull;

    for (int cb = 0; cb < 4; ++cb) {
        if (cb) __syncthreads();
        {
            const float4* ysrc = reinterpret_cast<const float4*>(g_y) + ((size_t)b * DIM + cb * 64) * N4;
            float4* yd = reinterpret_cast<float4*>(y_s);
            for (int i = t; i < 64 * N4; i += 512) yd[i] = ysrc[i];
            const float4* wsrc = reinterpret_cast<const float4*>(g_pwT);
            float4* wd = reinterpret_cast<float4*>(w_s);
            for (int i = t; i < 1024; i += 512) {
                int c = i >> 4, o4 = i & 15;
                wd[i] = wsrc[((cb * 64 + c) * DIM + ob * 64) / 4 + o4];
            }
        }
        __syncthreads();

        if (act) {
            const float4* y4 = reinterpret_cast<const float4*>(y_s);
            const float4* w4 = reinterpret_cast<const float4*>(w_s);
            #pragma unroll 2
            for (int c = 0; c < 64; ++c) {
                F4 yv; yv.v = y4[c * N4 + nt];
                ull yp[4];
                #pragma unroll
                for (int j = 0; j < 4; ++j) PACK2(yp[j], yv.f[j]);
                #pragma unroll
                for (int g = 0; g < 2; ++g) {
                    F4 wv; wv.v = w4[c * 16 + ot * 2 + g];
                    #pragma unroll
                    for (int half = 0; half < 2; ++half) {
                        const int p = g * 2 + half;
                        #pragma unroll
                        for (int j = 0; j < 4; ++j)
                            FMA2(acc[p][j], wv.u[half], yp[j]);
                    }
                }
            }
        }
    }

    if (act) {
        float4* out4 = reinterpret_cast<float4*>(out);
        #pragma unroll
        for (int p = 0; p < 4; ++p) {
            float lo[4], hi[4];
            #pragma unroll
            for (int j = 0; j < 4; ++j) UNPACK2(lo[j], hi[j], acc[p][j]);
            #pragma unroll
            for (int half = 0; half < 2; ++half) {
                int og = ob * 64 + ot * 8 + p * 2 + half;
                float tt = g_pt[og];
                const float* src = half ? hi : lo;
                out4[((size_t)b * DIM + og) * N4 + nt] =
                    make_float4(src[0] + tt, src[1] + tt, src[2] + tt, src[3] + tt);
            }
        }
    }
}

// ---------------- launcher ----------------
extern "C" void kernel_launch(void* const* d_in, const int* in_sizes, int n_in,
                              void* d_out, int out_size)
{
    const float* x       = (const float*)d_in[0];
    const float* qkv_w   = (const float*)d_in[1];
    const float* qkv_g   = (const float*)d_in[2];
    const float* qkv_b   = (const float*)d_in[3];
    const float* qkv_rm  = (const float*)d_in[4];
    const float* qkv_rv  = (const float*)d_in[5];
    const float* dw_w    = (const float*)d_in[6];
    const float* dw_g    = (const float*)d_in[7];
    const float* dw_b    = (const float*)d_in[8];
    const float* dw_rm   = (const float*)d_in[9];
    const float* dw_rv   = (const float*)d_in[10];
    const float* proj_w  = (const float*)d_in[11];
    const float* proj_g  = (const float*)d_in[12];
    const float* proj_b  = (const float*)d_in[13];
    const float* proj_rm = (const float*)d_in[14];
    const float* proj_rv = (const float*)d_in[15];
    const float* ab      = (const float*)d_in[16];
    const int*   bidx    = (const int*)d_in[17];
    float* out = (float*)d_out;

    cudaFuncSetAttribute(k_attn, cudaFuncAttributeMaxDynamicSharedMemorySize, SMEM_BYTES);
    cudaFuncSetAttribute(k_proj, cudaFuncAttributeMaxDynamicSharedMemorySize, PROJ_SMEM);

    k_pre<<<(HEADS * NPIX * NPIX + 255) / 256, 256>>>(ab, bidx, proj_w, proj_g, proj_b, proj_rm, proj_rv);
    k_attn<<<BATCH, NT, SMEM_BYTES>>>(x, qkv_w, qkv_g, qkv_b, qkv_rm, qkv_rv,
                                      dw_w, dw_g, dw_b, dw_rm, dw_rv);
    k_proj<<<dim3(BATCH, 4), 512, PROJ_SMEM>>>(out);
}